// round 1
// baseline (speedup 1.0000x reference)
#include <cuda_runtime.h>

#define NBv   8
#define ND    512
#define NCHv  3
#define NMIXv 4
#define HD    128

// ---------------- device scratch (no allocation allowed) ----------------
__device__ float4 g_feat[NBv * NCHv * ND];      // feature_xc, [b][k][a] -> 4 mix vals
__device__ float  g_h[NBv * NCHv * HD];         // h after mean+w1, [b][k*128+j]

__device__ __forceinline__ float ex2f(float x) {
    float r; asm("ex2.approx.f32 %0, %1;" : "=f"(r) : "f"(x)); return r;
}

// ---------------- kernel 1: pairwise SM-kernel + feature_xc ----------------
// grid (16 a-tiles, 3 ch, 8 batch), 256 threads.
// feature[b,a,k,m] = sum_c exp(-0.5*(2pi)^2 * |(x_a-x_c)*istd_m|^2)
//                          * cos(2pi*(x_a-x_c).mu_m) * yc[b,c,k]
//                  + ZITTER*yc[b,a,k]
__global__ void __launch_bounds__(256) k_pair(
    const float* __restrict__ xc, const float* __restrict__ yc,
    const float* __restrict__ mu, const float* __restrict__ istd)
{
    // per-point table: for each c: {u0,u1,cos,sin} per mix (4 float4) + {yc,...}
    __shared__ float4 tab[ND * 5];          // 40 KB
    __shared__ float4 red[8][32];           // 4 KB

    const int tile = blockIdx.x, k = blockIdx.y, b = blockIdx.z;
    const int tid = threadIdx.x;

    const float PI2   = 6.2831853071795864f;
    const float ALPHA = 5.3364464f;   // PI2 * sqrt(0.5 * log2(e))

    // ---- precompute point table for this (b,k) slab ----
    for (int c = tid; c < ND; c += 256) {
        const float x0 = xc[((b * ND + c) * 2 + 0) * NCHv + k];
        const float x1 = xc[((b * ND + c) * 2 + 1) * NCHv + k];
        const float y  = yc[(b * ND + c) * NCHv + k];
        #pragma unroll
        for (int m = 0; m < NMIXv; m++) {
            const float u0 = x0 * istd[2 * m + 0] * ALPHA;
            const float u1 = x1 * istd[2 * m + 1] * ALPHA;
            // phase in "turns"; reduce to [-0.5,0.5] so fast sincos is accurate
            float t = fmaf(x0, mu[2 * m + 0], x1 * mu[2 * m + 1]);
            t -= rintf(t);
            float sn, cn;
            __sincosf(PI2 * t, &sn, &cn);
            tab[c * 5 + m] = make_float4(u0, u1, cn, sn);
        }
        tab[c * 5 + 4] = make_float4(y, 0.f, 0.f, 0.f);
    }
    __syncthreads();

    // ---- pair loop: warp = 32 distinct a, uniform c-split (broadcast LDS) ----
    const int al = tid & 31;        // a within tile (lane)
    const int cs = tid >> 5;        // c-split 0..7 (uniform per warp)
    const int a  = tile * 32 + al;

    float4 A[NMIXv];
    #pragma unroll
    for (int m = 0; m < NMIXv; m++) A[m] = tab[a * 5 + m];

    float acc[NMIXv] = {0.f, 0.f, 0.f, 0.f};

    #pragma unroll 2
    for (int c = cs; c < ND; c += 8) {
        float4 C[NMIXv];
        #pragma unroll
        for (int m = 0; m < NMIXv; m++) C[m] = tab[c * 5 + m];
        const float ycv = tab[c * 5 + 4].x;
        #pragma unroll
        for (int m = 0; m < NMIXv; m++) {
            const float d0 = A[m].x - C[m].x;
            const float d1 = A[m].y - C[m].y;
            const float s  = fmaf(d1, -d1, (-d0) * d0);          // -(|du|^2), exp2 arg
            const float cv = fmaf(A[m].z, C[m].z, A[m].w * C[m].w); // cos(2pi dphase)
            acc[m] = fmaf(ex2f(s) * cv, ycv, acc[m]);
        }
    }

    red[cs][al] = make_float4(acc[0], acc[1], acc[2], acc[3]);
    __syncthreads();

    if (tid < 32) {
        float4 f = red[0][tid];
        #pragma unroll
        for (int j = 1; j < 8; j++) {
            const float4 g = red[j][tid];
            f.x += g.x; f.y += g.y; f.z += g.z; f.w += g.w;
        }
        const float yv = tab[(tile * 32 + tid) * 5 + 4].x;
        const float Z = 1.0e-4f;
        f.x += Z * yv; f.y += Z * yv; f.z += Z * yv; f.w += Z * yv;
        g_feat[(b * NCHv + k) * ND + tile * 32 + tid] = f;
    }
}

// ---------------- kernel 2: relu(feat @ w1^T + b1), mean over a ----------------
// grid 24 = (b,k), 512 threads: j = tid&127 (output neuron), q = tid>>7 (a split)
__global__ void __launch_bounds__(512) k_mlp1(
    const float* __restrict__ yc,
    const float* __restrict__ w1, const float* __restrict__ b1)
{
    __shared__ __align__(16) float4 sf[ND];
    __shared__ float sy[ND];
    __shared__ float sred[4][HD];

    const int bk = blockIdx.x, b = bk / NCHv, k = bk % NCHv;
    const int tid = threadIdx.x;

    for (int a = tid; a < ND; a += 512) {
        sf[a] = g_feat[bk * ND + a];
        sy[a] = yc[(b * ND + a) * NCHv + k];
    }
    __syncthreads();

    const int j = tid & 127, q = tid >> 7;
    const float wr0 = w1[j * 5 + 0], wr1 = w1[j * 5 + 1], wr2 = w1[j * 5 + 2];
    const float wr3 = w1[j * 5 + 3], wr4 = w1[j * 5 + 4], bb = b1[j];

    float acc = 0.f;
    #pragma unroll 4
    for (int a = q; a < ND; a += 4) {
        const float4 f = sf[a];
        const float y = sy[a];
        float h = fmaf(wr0, f.x, bb);
        h = fmaf(wr1, f.y, h);
        h = fmaf(wr2, f.z, h);
        h = fmaf(wr3, f.w, h);
        h = fmaf(wr4, y, h);
        acc += fmaxf(h, 0.f);
    }
    sred[q][j] = acc;
    __syncthreads();

    if (tid < HD) {
        const float s = (sred[0][tid] + sred[1][tid] + sred[2][tid] + sred[3][tid])
                        * (1.0f / 512.0f);
        g_h[b * (NCHv * HD) + k * HD + tid] = s;
    }
}

// ---------------- kernel 3: layers 2..5 ----------------
// grid 8 (batch), 128 threads (one per hidden unit)
__global__ void __launch_bounds__(128) k_mlp2(
    const float* __restrict__ w2, const float* __restrict__ b2,
    const float* __restrict__ w3, const float* __restrict__ b3,
    const float* __restrict__ w4, const float* __restrict__ b4,
    const float* __restrict__ w5, const float* __restrict__ b5,
    float* __restrict__ out)
{
    const int b = blockIdx.x, j = threadIdx.x;
    __shared__ __align__(16) float h1[NCHv * HD];
    __shared__ __align__(16) float h2[HD];
    __shared__ __align__(16) float h3[HD];
    __shared__ __align__(16) float h4[HD];

    for (int i = j; i < NCHv * HD; i += HD) h1[i] = g_h[b * NCHv * HD + i];
    __syncthreads();

    // layer 2: 384 -> 128
    {
        float acc = b2[j];
        const float4* wr = (const float4*)(w2 + j * (NCHv * HD));
        const float4* hv = (const float4*)h1;
        #pragma unroll 8
        for (int i = 0; i < (NCHv * HD) / 4; i++) {
            const float4 w = wr[i], x = hv[i];
            acc = fmaf(w.x, x.x, acc); acc = fmaf(w.y, x.y, acc);
            acc = fmaf(w.z, x.z, acc); acc = fmaf(w.w, x.w, acc);
        }
        h2[j] = fmaxf(acc, 0.f);
    }
    __syncthreads();

    // layer 3: 128 -> 128
    {
        float acc = b3[j];
        const float4* wr = (const float4*)(w3 + j * HD);
        const float4* hv = (const float4*)h2;
        #pragma unroll 8
        for (int i = 0; i < HD / 4; i++) {
            const float4 w = wr[i], x = hv[i];
            acc = fmaf(w.x, x.x, acc); acc = fmaf(w.y, x.y, acc);
            acc = fmaf(w.z, x.z, acc); acc = fmaf(w.w, x.w, acc);
        }
        h3[j] = fmaxf(acc, 0.f);
    }
    __syncthreads();

    // layer 4: 128 -> 128
    {
        float acc = b4[j];
        const float4* wr = (const float4*)(w4 + j * HD);
        const float4* hv = (const float4*)h3;
        #pragma unroll 8
        for (int i = 0; i < HD / 4; i++) {
            const float4 w = wr[i], x = hv[i];
            acc = fmaf(w.x, x.x, acc); acc = fmaf(w.y, x.y, acc);
            acc = fmaf(w.z, x.z, acc); acc = fmaf(w.w, x.w, acc);
        }
        h4[j] = fmaxf(acc, 0.f);
    }
    __syncthreads();

    // layer 5: 128 -> 12 (out[b][k*4+m])
    if (j < NCHv * NMIXv) {
        float acc = b5[j];
        const float4* wr = (const float4*)(w5 + j * HD);
        const float4* hv = (const float4*)h4;
        #pragma unroll 8
        for (int i = 0; i < HD / 4; i++) {
            const float4 w = wr[i], x = hv[i];
            acc = fmaf(w.x, x.x, acc); acc = fmaf(w.y, x.y, acc);
            acc = fmaf(w.z, x.z, acc); acc = fmaf(w.w, x.w, acc);
        }
        out[b * (NCHv * NMIXv) + j] = acc;
    }
}

// ---------------- launch ----------------
extern "C" void kernel_launch(void* const* d_in, const int* in_sizes, int n_in,
                              void* d_out, int out_size)
{
    const float* xc   = (const float*)d_in[0];
    const float* yc   = (const float*)d_in[1];
    const float* mu   = (const float*)d_in[2];
    const float* istd = (const float*)d_in[3];
    const float* w1   = (const float*)d_in[4];
    const float* b1   = (const float*)d_in[5];
    const float* w2   = (const float*)d_in[6];
    const float* b2   = (const float*)d_in[7];
    const float* w3   = (const float*)d_in[8];
    const float* b3   = (const float*)d_in[9];
    const float* w4   = (const float*)d_in[10];
    const float* b4   = (const float*)d_in[11];
    const float* w5   = (const float*)d_in[12];
    const float* b5   = (const float*)d_in[13];
    float* out = (float*)d_out;

    dim3 g1(ND / 32, NCHv, NBv);   // 16 x 3 x 8 = 384 blocks
    k_pair<<<g1, 256>>>(xc, yc, mu, istd);
    k_mlp1<<<NBv * NCHv, 512>>>(yc, w1, b1);
    k_mlp2<<<NBv, 128>>>(w2, b2, w3, b3, w4, b4, w5, b5, out);
}